// round 14
// baseline (speedup 1.0000x reference)
#include <cuda_runtime.h>
#include <cuda_fp16.h>
#include <cstdint>

#define NN 10000
#define TT 24
#define NE 320000
#define HH 64
#define G4 256   // 4*H
#define FULL 0xffffffffu

// ---------------- scratch ----------------
__device__ __half2 g_Hh[(size_t)TT * NN * 32];   // h * norm_src, fp16, per t
__device__ __half2 g_Zh[(size_t)TT * NN * 32];   // z0 * norm_src, fp16, per t
__device__ float   g_P[(size_t)NN * TT + 32];    // (z1*norm_src) . Wg2, [node][t]
__device__ int     g_deg_out[NN];
__device__ int     g_deg_in[NN];
__device__ int     g_cursor[NN];
__device__ int     g_offs[NN + 1];
__device__ int     g_csr[NE];                    // src indices grouped by dst
__device__ float   g_nsrc[NN];
__device__ float   g_ndst[NN];

// ---------------- helpers ----------------
__device__ __forceinline__ float tanh_fast(float x) {
    float y;
    asm("tanh.approx.f32 %0, %1;" : "=f"(y) : "f"(x));
    return y;
}
__device__ __forceinline__ float sigf(float x) {
    return fmaf(tanh_fast(0.5f * x), 0.5f, 0.5f);
}

__device__ __forceinline__ unsigned long long packf2(float lo, float hi) {
    unsigned long long r;
    asm("mov.b64 %0, {%1, %2};" : "=l"(r) : "f"(lo), "f"(hi));
    return r;
}
__device__ __forceinline__ void unpackf2(unsigned long long v, float& lo, float& hi) {
    asm("mov.b64 {%0, %1}, %2;" : "=f"(lo), "=f"(hi) : "l"(v));
}
__device__ __forceinline__ void fma2(unsigned long long& d, unsigned long long a,
                                     unsigned long long b) {
    asm("fma.rn.f32x2 %0, %1, %2, %0;" : "+l"(d) : "l"(a), "l"(b));
}

// ---------------- setup ----------------
__global__ void k_init() {
    int i = blockIdx.x * blockDim.x + threadIdx.x;
    if (i < NN) { g_deg_out[i] = 0; g_deg_in[i] = 0; g_cursor[i] = 0; }
}

__global__ void k_deg(const int* __restrict__ esrc, const int* __restrict__ edst) {
    int e = blockIdx.x * blockDim.x + threadIdx.x;
    if (e < NE) {
        atomicAdd(&g_deg_out[esrc[e]], 1);
        atomicAdd(&g_deg_in[edst[e]], 1);
    }
}

__global__ void k_norm() {
    int i = blockIdx.x * blockDim.x + threadIdx.x;
    if (i < NN) {
        int dout = g_deg_out[i], din = g_deg_in[i];
        g_nsrc[i] = (dout > 0) ? rsqrtf((float)dout) : 0.0f;
        g_ndst[i] = (din  > 0) ? rsqrtf((float)din)  : 0.0f;
    }
}

// ---------------- phase 1: per-node LSTM (proven 524us config, reg-pinned) ----------------
// 512 threads, 16 warps. Warp w owns gate rows 16w..16w+15; lanes 0-15 take
// half 0, lanes 16-31 half 1 of the same rows. Halves combine via
// shfl_xor(16). h fp32 in shared (broadcast LDS.128). Compiled at 64 regs;
// __launch_bounds__(512,2) pins the 2-CTA/SM residency.
__global__ void __launch_bounds__(512, 2) k_lstm(
    const float* __restrict__ blob,
    const float* __restrict__ Wih,
    const float* __restrict__ bih,
    const float* __restrict__ Whh,
    const float* __restrict__ bhh)
{
    int node = blockIdx.x;
    int tid  = threadIdx.x;
    int wid  = tid >> 5;
    int lane = tid & 31;
    int g    = wid * 16 + (lane & 15);   // gate row
    int half = lane >> 4;                // warp-uniform per half-warp
    int grp  = g >> 6;

    __shared__ __align__(16) float hf_sm[HH];
    __shared__ float act_sm[G4];
    __shared__ float x_sm[TT];

    // this half-row's 32 weights as 16 packed f32x2
    unsigned long long w[16];
    const ulonglong2* wp = (const ulonglong2*)
        (Whh + ((size_t)node * G4 + g) * HH + half * 32);
#pragma unroll
    for (int i = 0; i < 8; i++) {
        ulonglong2 v = wp[i];
        w[2 * i + 0] = v.x;
        w[2 * i + 1] = v.y;
    }
    float wx   = Wih[(size_t)node * G4 + g];
    float bias = bih[(size_t)node * G4 + g] + bhh[(size_t)node * G4 + g];
    float ns   = g_nsrc[node];

    if (tid < TT) x_sm[tid] = blob[node * TT + tid];
    float c = 0.0f;
    __syncthreads();

    __half* gH = (__half*)g_Hh;

    // ---- t = 0: h = 0, no weight contribution ----
    if (half == 0) {
        float gate = fmaf(wx, x_sm[0], bias);
        act_sm[g] = (grp == 2) ? tanh_fast(gate) : sigf(gate);
    }
    __syncthreads();
    if (tid < HH) {
        float I = act_sm[tid], G = act_sm[tid + 128], O = act_sm[tid + 192];
        c = I * G;
        float hv = O * tanh_fast(c);
        hf_sm[tid] = hv;
        gH[((size_t)0 * NN + node) * HH + tid] = __float2half_rn(hv * ns);
    }
    __syncthreads();

    for (int t = 1; t < TT; t++) {
        const float4* hp = (const float4*)(hf_sm + half * 32);
        unsigned long long acc0 = packf2(0.0f, 0.0f);
        unsigned long long acc1 = packf2(0.0f, 0.0f);
#pragma unroll
        for (int k = 0; k < 8; k++) {
            float4 hv = hp[k];
            fma2(acc0, packf2(hv.x, hv.y), w[2 * k + 0]);
            fma2(acc1, packf2(hv.z, hv.w), w[2 * k + 1]);
        }
        float a0, a1, a2, a3;
        unpackf2(acc0, a0, a1);
        unpackf2(acc1, a2, a3);
        float s = (a0 + a1) + (a2 + a3);
        s += __shfl_xor_sync(FULL, s, 16);   // combine the two half-rows

        if (half == 0) {
            float gate = fmaf(wx, x_sm[t], bias) + s;
            act_sm[g] = (grp == 2) ? tanh_fast(gate) : sigf(gate);
        }
        __syncthreads();
        if (tid < HH) {
            float I = act_sm[tid],       F = act_sm[tid + 64];
            float G = act_sm[tid + 128], O = act_sm[tid + 192];
            c = fmaf(F, c, I * G);
            float hv = O * tanh_fast(c);
            hf_sm[tid] = hv;
            gH[((size_t)t * NN + node) * HH + tid] = __float2half_rn(hv * ns);
        }
        __syncthreads();
    }
}

// ---------------- scan: 1024 threads, 10 nodes/thread ----------------
__global__ void k_scan() {
    __shared__ int warp_tot[32];
    int tid = threadIdx.x;
    const int PER = 10;
    int start = tid * PER;
    int sum = 0;
#pragma unroll
    for (int i = 0; i < PER; i++) {
        int n = start + i;
        if (n < NN) sum += g_deg_in[n];
    }
    int lane = tid & 31, w = tid >> 5;
    int inc = sum;
#pragma unroll
    for (int off = 1; off < 32; off <<= 1) {
        int v = __shfl_up_sync(FULL, inc, off);
        if (lane >= off) inc += v;
    }
    if (lane == 31) warp_tot[w] = inc;
    __syncthreads();
    if (w == 0) {
        int v = warp_tot[lane];
#pragma unroll
        for (int off = 1; off < 32; off <<= 1) {
            int u = __shfl_up_sync(FULL, v, off);
            if (lane >= off) v += u;
        }
        warp_tot[lane] = v;
    }
    __syncthreads();
    int base = inc - sum + ((w > 0) ? warp_tot[w - 1] : 0);
    int run = base;
    for (int i = 0; i < PER; i++) {
        int n = start + i;
        if (n < NN) { g_offs[n] = run; run += g_deg_in[n]; }
    }
    if (tid == 1023) g_offs[NN] = base;
}

__global__ void k_scatter(const int* __restrict__ esrc, const int* __restrict__ edst) {
    int e = blockIdx.x * blockDim.x + threadIdx.x;
    if (e < NE) {
        int d = edst[e];
        int pos = g_offs[d] + atomicAdd(&g_cursor[d], 1);
        g_csr[pos] = esrc[e];
    }
}

// ---------------- phase 2: t-pair fused gconv ----------------
// Block: 32 nodes x 2 timesteps (t0 = 2*blockIdx.y, t1 = t0+1).
// CSR indices + shfls shared across both t (index overhead halved, 8 loads
// in flight). GEMM: each Wsm float2 feeds 4 outputs (2 nodes x 2 t).
template<int MODE>
__global__ __launch_bounds__(256) void k_gconv(
    const float* __restrict__ W,
    const float* __restrict__ b,
    const float* __restrict__ Wg2)
{
    __shared__ float Wsm[HH * HH];
    __shared__ float bsm[HH];
    __shared__ float w2sm[HH];
    __shared__ __align__(16) float aggsm[8][2][2][HH];   // [warp][node][t][dim]

    int tid = threadIdx.x;
    int wp  = tid >> 5;
    int lane = tid & 31;
    int t0 = blockIdx.y * 2;

    for (int i = tid; i < HH * HH; i += 256) Wsm[i] = W[i];
    if (tid < HH) {
        bsm[tid] = b[tid];
        if (MODE == 1) w2sm[tid] = Wg2[tid];
    }
    __syncthreads();

    const __half2* __restrict__ X = (MODE == 0) ? g_Hh : g_Zh;
    const __half2* __restrict__ Xt0 = X + (size_t)t0 * NN * 32;
    const __half2* __restrict__ Xt1 = Xt0 + (size_t)NN * 32;

    for (int p = 0; p < 2; p++) {
        int nodeA = blockIdx.x * 32 + wp * 4 + 2 * p;
        int nodeB = nodeA + 1;

        // gather both nodes, both timesteps
#pragma unroll
        for (int s = 0; s < 2; s++) {
            int node = nodeA + s;
            if (node < NN) {
                int rs = g_offs[node], re = g_offs[node + 1];
                float ax0 = 0.f, ay0 = 0.f, ax1 = 0.f, ay1 = 0.f;   // t0
                float bx0 = 0.f, by0 = 0.f, bx1 = 0.f, by1 = 0.f;   // t1
                for (int base = rs; base < re; base += 32) {
                    int nloc = min(32, re - base);
                    int idx = (lane < nloc) ? g_csr[base + lane] : 0;
                    int j = 0;
                    for (; j + 4 <= nloc; j += 4) {
                        int s0 = __shfl_sync(FULL, idx, j + 0);
                        int s1 = __shfl_sync(FULL, idx, j + 1);
                        int s2 = __shfl_sync(FULL, idx, j + 2);
                        int s3 = __shfl_sync(FULL, idx, j + 3);
                        __half2 r0 = Xt0[(size_t)s0 * 32 + lane];
                        __half2 r1 = Xt0[(size_t)s1 * 32 + lane];
                        __half2 r2 = Xt0[(size_t)s2 * 32 + lane];
                        __half2 r3 = Xt0[(size_t)s3 * 32 + lane];
                        __half2 u0 = Xt1[(size_t)s0 * 32 + lane];
                        __half2 u1 = Xt1[(size_t)s1 * 32 + lane];
                        __half2 u2 = Xt1[(size_t)s2 * 32 + lane];
                        __half2 u3 = Xt1[(size_t)s3 * 32 + lane];
                        float2 v0 = __half22float2(r0);
                        float2 v1 = __half22float2(r1);
                        float2 v2 = __half22float2(r2);
                        float2 v3 = __half22float2(r3);
                        float2 q0 = __half22float2(u0);
                        float2 q1 = __half22float2(u1);
                        float2 q2 = __half22float2(u2);
                        float2 q3 = __half22float2(u3);
                        ax0 += v0.x + v1.x; ay0 += v0.y + v1.y;
                        ax1 += v2.x + v3.x; ay1 += v2.y + v3.y;
                        bx0 += q0.x + q1.x; by0 += q0.y + q1.y;
                        bx1 += q2.x + q3.x; by1 += q2.y + q3.y;
                    }
                    for (; j < nloc; j++) {
                        int sx = __shfl_sync(FULL, idx, j);
                        float2 v = __half22float2(Xt0[(size_t)sx * 32 + lane]);
                        float2 q = __half22float2(Xt1[(size_t)sx * 32 + lane]);
                        ax0 += v.x; ay0 += v.y;
                        bx0 += q.x; by0 += q.y;
                    }
                }
                float nd = g_ndst[node];
                aggsm[wp][s][0][2 * lane + 0] = (ax0 + ax1) * nd;
                aggsm[wp][s][0][2 * lane + 1] = (ay0 + ay1) * nd;
                aggsm[wp][s][1][2 * lane + 0] = (bx0 + bx1) * nd;
                aggsm[wp][s][1][2 * lane + 1] = (by0 + by1) * nd;
            }
        }
        __syncwarp();

        if (nodeA < NN) {
            bool haveB = (nodeB < NN);
            int d0 = 2 * lane;
            float bb0 = bsm[d0], bb1 = bsm[d0 + 1];
            float zA00 = bb0, zA01 = bb1;   // nodeA, t0
            float zA10 = bb0, zA11 = bb1;   // nodeA, t1
            float zB00 = bb0, zB01 = bb1;   // nodeB, t0
            float zB10 = bb0, zB11 = bb1;   // nodeB, t1
            const float4* aA0 = (const float4*)aggsm[wp][0][0];
            const float4* aA1 = (const float4*)aggsm[wp][0][1];
            const float4* aB0 = (const float4*)aggsm[wp][1][0];
            const float4* aB1 = (const float4*)aggsm[wp][1][1];
#pragma unroll
            for (int k4 = 0; k4 < 16; k4++) {
                float4 qa0 = aA0[k4];
                float4 qa1 = aA1[k4];
                float4 qb0 = aB0[k4];
                float4 qb1 = aB1[k4];
                float fa0[4] = {qa0.x, qa0.y, qa0.z, qa0.w};
                float fa1[4] = {qa1.x, qa1.y, qa1.z, qa1.w};
                float fb0[4] = {qb0.x, qb0.y, qb0.z, qb0.w};
                float fb1[4] = {qb1.x, qb1.y, qb1.z, qb1.w};
                int kb = k4 * 4;
#pragma unroll
                for (int kk = 0; kk < 4; kk++) {
                    float2 wv = ((const float2*)(Wsm + (kb + kk) * HH))[lane];
                    zA00 = fmaf(fa0[kk], wv.x, zA00); zA01 = fmaf(fa0[kk], wv.y, zA01);
                    zA10 = fmaf(fa1[kk], wv.x, zA10); zA11 = fmaf(fa1[kk], wv.y, zA11);
                    zB00 = fmaf(fb0[kk], wv.x, zB00); zB01 = fmaf(fb0[kk], wv.y, zB01);
                    zB10 = fmaf(fb1[kk], wv.x, zB10); zB11 = fmaf(fb1[kk], wv.y, zB11);
                }
            }

            float nsA = g_nsrc[nodeA];
            float nsB = haveB ? g_nsrc[nodeB] : 0.0f;
            zA00 = fmaxf(zA00, 0.0f) * nsA; zA01 = fmaxf(zA01, 0.0f) * nsA;
            zA10 = fmaxf(zA10, 0.0f) * nsA; zA11 = fmaxf(zA11, 0.0f) * nsA;
            zB00 = fmaxf(zB00, 0.0f) * nsB; zB01 = fmaxf(zB01, 0.0f) * nsB;
            zB10 = fmaxf(zB10, 0.0f) * nsB; zB11 = fmaxf(zB11, 0.0f) * nsB;

            if (MODE == 0) {
                g_Zh[((size_t)t0 * NN + nodeA) * 32 + lane] = __floats2half2_rn(zA00, zA01);
                g_Zh[((size_t)(t0 + 1) * NN + nodeA) * 32 + lane] = __floats2half2_rn(zA10, zA11);
                if (haveB) {
                    g_Zh[((size_t)t0 * NN + nodeB) * 32 + lane] = __floats2half2_rn(zB00, zB01);
                    g_Zh[((size_t)(t0 + 1) * NN + nodeB) * 32 + lane] = __floats2half2_rn(zB10, zB11);
                }
            } else {
                float w20 = w2sm[d0], w21 = w2sm[d0 + 1];
                float pA0 = zA00 * w20 + zA01 * w21;
                float pA1 = zA10 * w20 + zA11 * w21;
                float pB0 = zB00 * w20 + zB01 * w21;
                float pB1 = zB10 * w20 + zB11 * w21;
#pragma unroll
                for (int off = 16; off >= 1; off >>= 1) {
                    pA0 += __shfl_xor_sync(FULL, pA0, off);
                    pA1 += __shfl_xor_sync(FULL, pA1, off);
                    pB0 += __shfl_xor_sync(FULL, pB0, off);
                    pB1 += __shfl_xor_sync(FULL, pB1, off);
                }
                if (lane == 0) {
                    g_P[(size_t)nodeA * TT + t0]     = pA0;
                    g_P[(size_t)nodeA * TT + t0 + 1] = pA1;
                    if (haveB) {
                        g_P[(size_t)nodeB * TT + t0]     = pB0;
                        g_P[(size_t)nodeB * TT + t0 + 1] = pB1;
                    }
                }
            }
        }
        __syncwarp();
    }
}

// ---------------- final: warp-per-node, lane = t ----------------
__global__ __launch_bounds__(256) void k_final(float* __restrict__ out,
                                               const float* __restrict__ bg2) {
    int node = blockIdx.x * 8 + (threadIdx.x >> 5);
    int lane = threadIdx.x & 31;
    if (node >= NN) return;

    int rs = g_offs[node], re = g_offs[node + 1];
    float s0 = 0.f, s1 = 0.f, s2 = 0.f, s3 = 0.f;

    for (int base = rs; base < re; base += 32) {
        int nloc = min(32, re - base);
        int idx = (lane < nloc) ? g_csr[base + lane] : 0;
        int j = 0;
        for (; j + 4 <= nloc; j += 4) {
            int a0 = __shfl_sync(FULL, idx, j + 0);
            int a1 = __shfl_sync(FULL, idx, j + 1);
            int a2 = __shfl_sync(FULL, idx, j + 2);
            int a3 = __shfl_sync(FULL, idx, j + 3);
            s0 += g_P[(size_t)a0 * TT + lane];
            s1 += g_P[(size_t)a1 * TT + lane];
            s2 += g_P[(size_t)a2 * TT + lane];
            s3 += g_P[(size_t)a3 * TT + lane];
        }
        for (; j < nloc; j++) {
            int a = __shfl_sync(FULL, idx, j);
            s0 += g_P[(size_t)a * TT + lane];
        }
    }
    float s = (s0 + s1) + (s2 + s3);
    if (lane < TT)
        out[node * TT + lane] = g_ndst[node] * s + bg2[0];
}

// ---------------- launch ----------------
extern "C" void kernel_launch(void* const* d_in, const int* in_sizes, int n_in,
                              void* d_out, int out_size)
{
    const float* blob = (const float*)d_in[0];
    const float* Wih  = (const float*)d_in[1];
    const float* bih  = (const float*)d_in[2];
    const float* Whh  = (const float*)d_in[3];
    const float* bhh  = (const float*)d_in[4];
    const float* Wg0  = (const float*)d_in[5];
    const float* bg0  = (const float*)d_in[6];
    const float* Wg1  = (const float*)d_in[7];
    const float* bg1  = (const float*)d_in[8];
    const float* Wg2  = (const float*)d_in[9];
    const float* bg2  = (const float*)d_in[10];
    const int*   esrc = (const int*)d_in[11];
    const int*   edst = (const int*)d_in[12];
    float* out = (float*)d_out;

    k_init<<<(NN + 255) / 256, 256>>>();
    k_deg<<<(NE + 255) / 256, 256>>>(esrc, edst);
    k_norm<<<(NN + 255) / 256, 256>>>();

    // LSTM stays in the ncu capture slot
    k_lstm<<<NN, 512>>>(blob, Wih, bih, Whh, bhh);

    k_scan<<<1, 1024>>>();
    k_scatter<<<(NE + 255) / 256, 256>>>(esrc, edst);

    dim3 gg((NN + 31) / 32, TT / 2);
    k_gconv<0><<<gg, 256>>>(Wg0, bg0, nullptr);
    k_gconv<1><<<gg, 256>>>(Wg1, bg1, Wg2);

    k_final<<<(NN + 7) / 8, 256>>>(out, bg2);
}

// round 16
// speedup vs baseline: 1.3627x; 1.3627x over previous
#include <cuda_runtime.h>
#include <cuda_fp16.h>
#include <cstdint>

#define NN 10000
#define TT 24
#define NE 320000
#define HH 64
#define G4 256   // 4*H
#define FULL 0xffffffffu

// ---------------- scratch ----------------
__device__ __half2 g_Hh[(size_t)TT * NN * 32];   // h * norm_src, fp16, per t
__device__ __half2 g_Zh[(size_t)TT * NN * 32];   // z0 * norm_src, fp16, per t
__device__ float   g_P[(size_t)NN * TT + 32];    // (z1*norm_src) . Wg2, [node][t]
__device__ int     g_deg_out[NN];
__device__ int     g_deg_in[NN];
__device__ int     g_cursor[NN];
__device__ int     g_offs[NN + 1];
__device__ int     g_csr[NE];                    // src indices grouped by dst
__device__ float   g_nsrc[NN];
__device__ float   g_ndst[NN];

// ---------------- helpers ----------------
__device__ __forceinline__ float tanh_fast(float x) {
    float y;
    asm("tanh.approx.f32 %0, %1;" : "=f"(y) : "f"(x));
    return y;
}
__device__ __forceinline__ float sigf(float x) {
    return fmaf(tanh_fast(0.5f * x), 0.5f, 0.5f);
}

__device__ __forceinline__ unsigned long long packf2(float lo, float hi) {
    unsigned long long r;
    asm("mov.b64 %0, {%1, %2};" : "=l"(r) : "f"(lo), "f"(hi));
    return r;
}
__device__ __forceinline__ void unpackf2(unsigned long long v, float& lo, float& hi) {
    asm("mov.b64 {%0, %1}, %2;" : "=f"(lo), "=f"(hi) : "l"(v));
}
__device__ __forceinline__ void fma2(unsigned long long& d, unsigned long long a,
                                     unsigned long long b) {
    asm("fma.rn.f32x2 %0, %1, %2, %0;" : "+l"(d) : "l"(a), "l"(b));
}

// ---------------- setup ----------------
__global__ void k_init() {
    int i = blockIdx.x * blockDim.x + threadIdx.x;
    if (i < NN) { g_deg_out[i] = 0; g_deg_in[i] = 0; g_cursor[i] = 0; }
}

__global__ void k_deg(const int* __restrict__ esrc, const int* __restrict__ edst) {
    int e = blockIdx.x * blockDim.x + threadIdx.x;
    if (e < NE) {
        atomicAdd(&g_deg_out[esrc[e]], 1);
        atomicAdd(&g_deg_in[edst[e]], 1);
    }
}

__global__ void k_norm() {
    int i = blockIdx.x * blockDim.x + threadIdx.x;
    if (i < NN) {
        int dout = g_deg_out[i], din = g_deg_in[i];
        g_nsrc[i] = (dout > 0) ? rsqrtf((float)dout) : 0.0f;
        g_ndst[i] = (din  > 0) ? rsqrtf((float)din)  : 0.0f;
    }
}

// ---------------- phase 1: per-node LSTM (exact R11 524us config; NO minBlocks pin) ----------------
// 512 threads, 16 warps. Warp w owns gate rows 16w..16w+15; lanes 0-15 take
// half 0, lanes 16-31 half 1 of the same rows. Halves combine via
// shfl_xor(16). h fp32 in shared (broadcast LDS.128). Natural alloc = 64 regs
// -> 2 CTAs/SM. (launch_bounds minBlocks pin de-pipelines ptxas; never add.)
__global__ void __launch_bounds__(512) k_lstm(
    const float* __restrict__ blob,
    const float* __restrict__ Wih,
    const float* __restrict__ bih,
    const float* __restrict__ Whh,
    const float* __restrict__ bhh)
{
    int node = blockIdx.x;
    int tid  = threadIdx.x;
    int wid  = tid >> 5;
    int lane = tid & 31;
    int g    = wid * 16 + (lane & 15);   // gate row
    int half = lane >> 4;                // warp-uniform per half-warp
    int grp  = g >> 6;

    __shared__ __align__(16) float hf_sm[HH];
    __shared__ float act_sm[G4];
    __shared__ float x_sm[TT];

    // this half-row's 32 weights as 16 packed f32x2
    unsigned long long w[16];
    const ulonglong2* wp = (const ulonglong2*)
        (Whh + ((size_t)node * G4 + g) * HH + half * 32);
#pragma unroll
    for (int i = 0; i < 8; i++) {
        ulonglong2 v = wp[i];
        w[2 * i + 0] = v.x;
        w[2 * i + 1] = v.y;
    }
    float wx   = Wih[(size_t)node * G4 + g];
    float bias = bih[(size_t)node * G4 + g] + bhh[(size_t)node * G4 + g];
    float ns   = g_nsrc[node];

    if (tid < TT) x_sm[tid] = blob[node * TT + tid];
    float c = 0.0f;
    __syncthreads();

    __half* gH = (__half*)g_Hh;

    // ---- t = 0: h = 0, no weight contribution ----
    if (half == 0) {
        float gate = fmaf(wx, x_sm[0], bias);
        act_sm[g] = (grp == 2) ? tanh_fast(gate) : sigf(gate);
    }
    __syncthreads();
    if (tid < HH) {
        float I = act_sm[tid], G = act_sm[tid + 128], O = act_sm[tid + 192];
        c = I * G;
        float hv = O * tanh_fast(c);
        hf_sm[tid] = hv;
        gH[((size_t)0 * NN + node) * HH + tid] = __float2half_rn(hv * ns);
    }
    __syncthreads();

    for (int t = 1; t < TT; t++) {
        const float4* hp = (const float4*)(hf_sm + half * 32);
        unsigned long long acc0 = packf2(0.0f, 0.0f);
        unsigned long long acc1 = packf2(0.0f, 0.0f);
#pragma unroll
        for (int k = 0; k < 8; k++) {
            float4 hv = hp[k];
            fma2(acc0, packf2(hv.x, hv.y), w[2 * k + 0]);
            fma2(acc1, packf2(hv.z, hv.w), w[2 * k + 1]);
        }
        float a0, a1, a2, a3;
        unpackf2(acc0, a0, a1);
        unpackf2(acc1, a2, a3);
        float s = (a0 + a1) + (a2 + a3);
        s += __shfl_xor_sync(FULL, s, 16);   // combine the two half-rows

        if (half == 0) {
            float gate = fmaf(wx, x_sm[t], bias) + s;
            act_sm[g] = (grp == 2) ? tanh_fast(gate) : sigf(gate);
        }
        __syncthreads();
        if (tid < HH) {
            float I = act_sm[tid],       F = act_sm[tid + 64];
            float G = act_sm[tid + 128], O = act_sm[tid + 192];
            c = fmaf(F, c, I * G);
            float hv = O * tanh_fast(c);
            hf_sm[tid] = hv;
            gH[((size_t)t * NN + node) * HH + tid] = __float2half_rn(hv * ns);
        }
        __syncthreads();
    }
}

// ---------------- scan: 1024 threads, 10 nodes/thread ----------------
__global__ void k_scan() {
    __shared__ int warp_tot[32];
    int tid = threadIdx.x;
    const int PER = 10;
    int start = tid * PER;
    int sum = 0;
#pragma unroll
    for (int i = 0; i < PER; i++) {
        int n = start + i;
        if (n < NN) sum += g_deg_in[n];
    }
    int lane = tid & 31, w = tid >> 5;
    int inc = sum;
#pragma unroll
    for (int off = 1; off < 32; off <<= 1) {
        int v = __shfl_up_sync(FULL, inc, off);
        if (lane >= off) inc += v;
    }
    if (lane == 31) warp_tot[w] = inc;
    __syncthreads();
    if (w == 0) {
        int v = warp_tot[lane];
#pragma unroll
        for (int off = 1; off < 32; off <<= 1) {
            int u = __shfl_up_sync(FULL, v, off);
            if (lane >= off) v += u;
        }
        warp_tot[lane] = v;
    }
    __syncthreads();
    int base = inc - sum + ((w > 0) ? warp_tot[w - 1] : 0);
    int run = base;
    for (int i = 0; i < PER; i++) {
        int n = start + i;
        if (n < NN) { g_offs[n] = run; run += g_deg_in[n]; }
    }
    if (tid == 1023) g_offs[NN] = base;
}

__global__ void k_scatter(const int* __restrict__ esrc, const int* __restrict__ edst) {
    int e = blockIdx.x * blockDim.x + threadIdx.x;
    if (e < NE) {
        int d = edst[e];
        int pos = g_offs[d] + atomicAdd(&g_cursor[d], 1);
        g_csr[pos] = esrc[e];
    }
}

// ---------------- phase 2: warp handles 4 nodes (as 2 pairs); fused gconv ----------------
// R11 structure; ONLY change: gather inner loop unrolled 8-deep (8 loads in
// flight before the adds) with 4-wide + scalar cleanup.
template<int MODE>
__global__ __launch_bounds__(256) void k_gconv(
    const float* __restrict__ W,
    const float* __restrict__ b,
    const float* __restrict__ Wg2)
{
    __shared__ float Wsm[HH * HH];
    __shared__ float bsm[HH];
    __shared__ float w2sm[HH];
    __shared__ __align__(16) float aggsm[8][2][HH];

    int tid = threadIdx.x;
    int wp  = tid >> 5;
    int lane = tid & 31;
    int t = blockIdx.y;

    for (int i = tid; i < HH * HH; i += 256) Wsm[i] = W[i];
    if (tid < HH) {
        bsm[tid] = b[tid];
        if (MODE == 1) w2sm[tid] = Wg2[tid];
    }
    __syncthreads();

    const __half2* __restrict__ Xt =
        ((MODE == 0) ? g_Hh : g_Zh) + (size_t)t * NN * 32;

    for (int p = 0; p < 2; p++) {
        int nodeA = blockIdx.x * 32 + wp * 4 + 2 * p;
        int nodeB = nodeA + 1;

#pragma unroll
        for (int s = 0; s < 2; s++) {
            int node = nodeA + s;
            if (node < NN) {
                int rs = g_offs[node], re = g_offs[node + 1];
                float ax0 = 0.f, ay0 = 0.f, ax1 = 0.f, ay1 = 0.f;
                for (int base = rs; base < re; base += 32) {
                    int nloc = min(32, re - base);
                    int idx = (lane < nloc) ? g_csr[base + lane] : 0;
                    int j = 0;
                    for (; j + 8 <= nloc; j += 8) {
                        int s0 = __shfl_sync(FULL, idx, j + 0);
                        int s1 = __shfl_sync(FULL, idx, j + 1);
                        int s2 = __shfl_sync(FULL, idx, j + 2);
                        int s3 = __shfl_sync(FULL, idx, j + 3);
                        int s4 = __shfl_sync(FULL, idx, j + 4);
                        int s5 = __shfl_sync(FULL, idx, j + 5);
                        int s6 = __shfl_sync(FULL, idx, j + 6);
                        int s7 = __shfl_sync(FULL, idx, j + 7);
                        __half2 r0 = Xt[(size_t)s0 * 32 + lane];
                        __half2 r1 = Xt[(size_t)s1 * 32 + lane];
                        __half2 r2 = Xt[(size_t)s2 * 32 + lane];
                        __half2 r3 = Xt[(size_t)s3 * 32 + lane];
                        __half2 r4 = Xt[(size_t)s4 * 32 + lane];
                        __half2 r5 = Xt[(size_t)s5 * 32 + lane];
                        __half2 r6 = Xt[(size_t)s6 * 32 + lane];
                        __half2 r7 = Xt[(size_t)s7 * 32 + lane];
                        float2 v0 = __half22float2(r0);
                        float2 v1 = __half22float2(r1);
                        float2 v2 = __half22float2(r2);
                        float2 v3 = __half22float2(r3);
                        float2 v4 = __half22float2(r4);
                        float2 v5 = __half22float2(r5);
                        float2 v6 = __half22float2(r6);
                        float2 v7 = __half22float2(r7);
                        ax0 += (v0.x + v1.x) + (v2.x + v3.x);
                        ay0 += (v0.y + v1.y) + (v2.y + v3.y);
                        ax1 += (v4.x + v5.x) + (v6.x + v7.x);
                        ay1 += (v4.y + v5.y) + (v6.y + v7.y);
                    }
                    for (; j + 4 <= nloc; j += 4) {
                        int s0 = __shfl_sync(FULL, idx, j + 0);
                        int s1 = __shfl_sync(FULL, idx, j + 1);
                        int s2 = __shfl_sync(FULL, idx, j + 2);
                        int s3 = __shfl_sync(FULL, idx, j + 3);
                        float2 v0 = __half22float2(Xt[(size_t)s0 * 32 + lane]);
                        float2 v1 = __half22float2(Xt[(size_t)s1 * 32 + lane]);
                        float2 v2 = __half22float2(Xt[(size_t)s2 * 32 + lane]);
                        float2 v3 = __half22float2(Xt[(size_t)s3 * 32 + lane]);
                        ax0 += v0.x + v1.x; ay0 += v0.y + v1.y;
                        ax1 += v2.x + v3.x; ay1 += v2.y + v3.y;
                    }
                    for (; j < nloc; j++) {
                        int sx = __shfl_sync(FULL, idx, j);
                        float2 v = __half22float2(Xt[(size_t)sx * 32 + lane]);
                        ax0 += v.x; ay0 += v.y;
                    }
                }
                float nd = g_ndst[node];
                aggsm[wp][s][2 * lane + 0] = (ax0 + ax1) * nd;
                aggsm[wp][s][2 * lane + 1] = (ay0 + ay1) * nd;
            }
        }
        __syncwarp();

        if (nodeA < NN) {
            bool haveB = (nodeB < NN);
            int d0 = 2 * lane;
            float za0 = bsm[d0], za1 = bsm[d0 + 1];
            float zb0 = za0, zb1 = za1;
            const float4* aA = (const float4*)aggsm[wp][0];
            const float4* aB = (const float4*)aggsm[wp][1];
#pragma unroll
            for (int k4 = 0; k4 < 16; k4++) {
                float4 a = aA[k4];
                float4 bb = aB[k4];
                int kb = k4 * 4;
                float2 w0 = ((const float2*)(Wsm + (kb + 0) * HH))[lane];
                float2 w1 = ((const float2*)(Wsm + (kb + 1) * HH))[lane];
                float2 w2 = ((const float2*)(Wsm + (kb + 2) * HH))[lane];
                float2 w3 = ((const float2*)(Wsm + (kb + 3) * HH))[lane];
                za0 = fmaf(a.x, w0.x, za0); za1 = fmaf(a.x, w0.y, za1);
                zb0 = fmaf(bb.x, w0.x, zb0); zb1 = fmaf(bb.x, w0.y, zb1);
                za0 = fmaf(a.y, w1.x, za0); za1 = fmaf(a.y, w1.y, za1);
                zb0 = fmaf(bb.y, w1.x, zb0); zb1 = fmaf(bb.y, w1.y, zb1);
                za0 = fmaf(a.z, w2.x, za0); za1 = fmaf(a.z, w2.y, za1);
                zb0 = fmaf(bb.z, w2.x, zb0); zb1 = fmaf(bb.z, w2.y, zb1);
                za0 = fmaf(a.w, w3.x, za0); za1 = fmaf(a.w, w3.y, za1);
                zb0 = fmaf(bb.w, w3.x, zb0); zb1 = fmaf(bb.w, w3.y, zb1);
            }

            float nsA = g_nsrc[nodeA];
            za0 = fmaxf(za0, 0.0f) * nsA;
            za1 = fmaxf(za1, 0.0f) * nsA;
            float nsB = haveB ? g_nsrc[nodeB] : 0.0f;
            zb0 = fmaxf(zb0, 0.0f) * nsB;
            zb1 = fmaxf(zb1, 0.0f) * nsB;

            if (MODE == 0) {
                g_Zh[((size_t)t * NN + nodeA) * 32 + lane] = __floats2half2_rn(za0, za1);
                if (haveB)
                    g_Zh[((size_t)t * NN + nodeB) * 32 + lane] = __floats2half2_rn(zb0, zb1);
            } else {
                float pa = za0 * w2sm[d0] + za1 * w2sm[d0 + 1];
                float pb = zb0 * w2sm[d0] + zb1 * w2sm[d0 + 1];
#pragma unroll
                for (int off = 16; off >= 1; off >>= 1) {
                    pa += __shfl_xor_sync(FULL, pa, off);
                    pb += __shfl_xor_sync(FULL, pb, off);
                }
                if (lane == 0) {
                    g_P[(size_t)nodeA * TT + t] = pa;
                    if (haveB) g_P[(size_t)nodeB * TT + t] = pb;
                }
            }
        }
        __syncwarp();
    }
}

// ---------------- final: warp-per-node, lane = t ----------------
__global__ __launch_bounds__(256) void k_final(float* __restrict__ out,
                                               const float* __restrict__ bg2) {
    int node = blockIdx.x * 8 + (threadIdx.x >> 5);
    int lane = threadIdx.x & 31;
    if (node >= NN) return;

    int rs = g_offs[node], re = g_offs[node + 1];
    float s0 = 0.f, s1 = 0.f, s2 = 0.f, s3 = 0.f;

    for (int base = rs; base < re; base += 32) {
        int nloc = min(32, re - base);
        int idx = (lane < nloc) ? g_csr[base + lane] : 0;
        int j = 0;
        for (; j + 4 <= nloc; j += 4) {
            int a0 = __shfl_sync(FULL, idx, j + 0);
            int a1 = __shfl_sync(FULL, idx, j + 1);
            int a2 = __shfl_sync(FULL, idx, j + 2);
            int a3 = __shfl_sync(FULL, idx, j + 3);
            s0 += g_P[(size_t)a0 * TT + lane];
            s1 += g_P[(size_t)a1 * TT + lane];
            s2 += g_P[(size_t)a2 * TT + lane];
            s3 += g_P[(size_t)a3 * TT + lane];
        }
        for (; j < nloc; j++) {
            int a = __shfl_sync(FULL, idx, j);
            s0 += g_P[(size_t)a * TT + lane];
        }
    }
    float s = (s0 + s1) + (s2 + s3);
    if (lane < TT)
        out[node * TT + lane] = g_ndst[node] * s + bg2[0];
}

// ---------------- launch ----------------
extern "C" void kernel_launch(void* const* d_in, const int* in_sizes, int n_in,
                              void* d_out, int out_size)
{
    const float* blob = (const float*)d_in[0];
    const float* Wih  = (const float*)d_in[1];
    const float* bih  = (const float*)d_in[2];
    const float* Whh  = (const float*)d_in[3];
    const float* bhh  = (const float*)d_in[4];
    const float* Wg0  = (const float*)d_in[5];
    const float* bg0  = (const float*)d_in[6];
    const float* Wg1  = (const float*)d_in[7];
    const float* bg1  = (const float*)d_in[8];
    const float* Wg2  = (const float*)d_in[9];
    const float* bg2  = (const float*)d_in[10];
    const int*   esrc = (const int*)d_in[11];
    const int*   edst = (const int*)d_in[12];
    float* out = (float*)d_out;

    k_init<<<(NN + 255) / 256, 256>>>();
    k_deg<<<(NE + 255) / 256, 256>>>(esrc, edst);
    k_norm<<<(NN + 255) / 256, 256>>>();

    // LSTM stays in the ncu capture slot
    k_lstm<<<NN, 512>>>(blob, Wih, bih, Whh, bhh);

    k_scan<<<1, 1024>>>();
    k_scatter<<<(NE + 255) / 256, 256>>>(esrc, edst);

    dim3 gg((NN + 31) / 32, TT);
    k_gconv<0><<<gg, 256>>>(Wg0, bg0, nullptr);
    k_gconv<1><<<gg, 256>>>(Wg1, bg1, Wg2);

    k_final<<<(NN + 7) / 8, 256>>>(out, bg2);
}

// round 17
// speedup vs baseline: 1.3724x; 1.0071x over previous
#include <cuda_runtime.h>
#include <cuda_fp16.h>
#include <cstdint>

#define NN 10000
#define TT 24
#define NE 320000
#define HH 64
#define G4 256   // 4*H
#define FULL 0xffffffffu

// ---------------- scratch ----------------
__device__ __half2 g_Hh[(size_t)TT * NN * 32];   // h * norm_src, fp16, per t
__device__ __half2 g_Zh[(size_t)TT * NN * 32];   // z0 * norm_src, fp16, per t
__device__ float   g_P[(size_t)NN * TT + 32];    // (z1*norm_src) . Wg2, [node][t]
__device__ int     g_deg_out[NN];
__device__ int     g_deg_in[NN];
__device__ int     g_cursor[NN];
__device__ int     g_offs[NN + 1];
__device__ int     g_csr[NE];                    // src indices grouped by dst
__device__ float   g_nsrc[NN];
__device__ float   g_ndst[NN];

// ---------------- helpers ----------------
__device__ __forceinline__ float tanh_fast(float x) {
    float y;
    asm("tanh.approx.f32 %0, %1;" : "=f"(y) : "f"(x));
    return y;
}
__device__ __forceinline__ float sigf(float x) {
    return fmaf(tanh_fast(0.5f * x), 0.5f, 0.5f);
}

__device__ __forceinline__ unsigned long long packf2(float lo, float hi) {
    unsigned long long r;
    asm("mov.b64 %0, {%1, %2};" : "=l"(r) : "f"(lo), "f"(hi));
    return r;
}
__device__ __forceinline__ void unpackf2(unsigned long long v, float& lo, float& hi) {
    asm("mov.b64 {%0, %1}, %2;" : "=f"(lo), "=f"(hi) : "l"(v));
}
__device__ __forceinline__ void fma2(unsigned long long& d, unsigned long long a,
                                     unsigned long long b) {
    asm("fma.rn.f32x2 %0, %1, %2, %0;" : "+l"(d) : "l"(a), "l"(b));
}

// ---------------- setup ----------------
__global__ void k_init() {
    int i = blockIdx.x * blockDim.x + threadIdx.x;
    if (i < NN) { g_deg_out[i] = 0; g_deg_in[i] = 0; g_cursor[i] = 0; }
}

__global__ void k_deg(const int* __restrict__ esrc, const int* __restrict__ edst) {
    int e = blockIdx.x * blockDim.x + threadIdx.x;
    if (e < NE) {
        atomicAdd(&g_deg_out[esrc[e]], 1);
        atomicAdd(&g_deg_in[edst[e]], 1);
    }
}

__global__ void k_norm() {
    int i = blockIdx.x * blockDim.x + threadIdx.x;
    if (i < NN) {
        int dout = g_deg_out[i], din = g_deg_in[i];
        g_nsrc[i] = (dout > 0) ? rsqrtf((float)dout) : 0.0f;
        g_ndst[i] = (din  > 0) ? rsqrtf((float)din)  : 0.0f;
    }
}

// ---------------- phase 1: per-node LSTM ----------------
// R11/R16 proven structure (64 regs natural, NO minBlocks pin). Single change:
// hf_sm padded to 72 floats — half 1's copy of h starts at float 36 (+16B),
// so the warp's two broadcast addresses land on disjoint banks
// (half0 chunk k: banks 4k..4k+3; half1: 4k+4..4k+7) -> 1 wavefront/LDS.128.
__global__ void __launch_bounds__(512) k_lstm(
    const float* __restrict__ blob,
    const float* __restrict__ Wih,
    const float* __restrict__ bih,
    const float* __restrict__ Whh,
    const float* __restrict__ bhh)
{
    int node = blockIdx.x;
    int tid  = threadIdx.x;
    int wid  = tid >> 5;
    int lane = tid & 31;
    int g    = wid * 16 + (lane & 15);   // gate row
    int half = lane >> 4;                // warp-uniform per half-warp
    int grp  = g >> 6;

    __shared__ __align__(16) float hf_sm[72];    // h[64], half1 padded +4
    __shared__ float act_sm[G4];
    __shared__ float x_sm[TT];

    // this half-row's 32 weights as 16 packed f32x2
    unsigned long long w[16];
    const ulonglong2* wp = (const ulonglong2*)
        (Whh + ((size_t)node * G4 + g) * HH + half * 32);
#pragma unroll
    for (int i = 0; i < 8; i++) {
        ulonglong2 v = wp[i];
        w[2 * i + 0] = v.x;
        w[2 * i + 1] = v.y;
    }
    float wx   = Wih[(size_t)node * G4 + g];
    float bias = bih[(size_t)node * G4 + g] + bhh[(size_t)node * G4 + g];
    float ns   = g_nsrc[node];

    if (tid < TT) x_sm[tid] = blob[node * TT + tid];
    float c = 0.0f;
    __syncthreads();

    __half* gH = (__half*)g_Hh;

    // ---- t = 0: h = 0, no weight contribution ----
    if (half == 0) {
        float gate = fmaf(wx, x_sm[0], bias);
        act_sm[g] = (grp == 2) ? tanh_fast(gate) : sigf(gate);
    }
    __syncthreads();
    if (tid < HH) {
        float I = act_sm[tid], G = act_sm[tid + 128], O = act_sm[tid + 192];
        c = I * G;
        float hv = O * tanh_fast(c);
        hf_sm[tid + ((tid >> 5) << 2)] = hv;     // padded slot
        gH[((size_t)0 * NN + node) * HH + tid] = __float2half_rn(hv * ns);
    }
    __syncthreads();

    for (int t = 1; t < TT; t++) {
        const float4* hp = (const float4*)(hf_sm + half * 36);  // 144B, 16B-aligned
        unsigned long long acc0 = packf2(0.0f, 0.0f);
        unsigned long long acc1 = packf2(0.0f, 0.0f);
#pragma unroll
        for (int k = 0; k < 8; k++) {
            float4 hv = hp[k];
            fma2(acc0, packf2(hv.x, hv.y), w[2 * k + 0]);
            fma2(acc1, packf2(hv.z, hv.w), w[2 * k + 1]);
        }
        float a0, a1, a2, a3;
        unpackf2(acc0, a0, a1);
        unpackf2(acc1, a2, a3);
        float s = (a0 + a1) + (a2 + a3);
        s += __shfl_xor_sync(FULL, s, 16);   // combine the two half-rows

        if (half == 0) {
            float gate = fmaf(wx, x_sm[t], bias) + s;
            act_sm[g] = (grp == 2) ? tanh_fast(gate) : sigf(gate);
        }
        __syncthreads();
        if (tid < HH) {
            float I = act_sm[tid],       F = act_sm[tid + 64];
            float G = act_sm[tid + 128], O = act_sm[tid + 192];
            c = fmaf(F, c, I * G);
            float hv = O * tanh_fast(c);
            hf_sm[tid + ((tid >> 5) << 2)] = hv;
            gH[((size_t)t * NN + node) * HH + tid] = __float2half_rn(hv * ns);
        }
        __syncthreads();
    }
}

// ---------------- scan: 1024 threads, 10 nodes/thread ----------------
__global__ void k_scan() {
    __shared__ int warp_tot[32];
    int tid = threadIdx.x;
    const int PER = 10;
    int start = tid * PER;
    int sum = 0;
#pragma unroll
    for (int i = 0; i < PER; i++) {
        int n = start + i;
        if (n < NN) sum += g_deg_in[n];
    }
    int lane = tid & 31, w = tid >> 5;
    int inc = sum;
#pragma unroll
    for (int off = 1; off < 32; off <<= 1) {
        int v = __shfl_up_sync(FULL, inc, off);
        if (lane >= off) inc += v;
    }
    if (lane == 31) warp_tot[w] = inc;
    __syncthreads();
    if (w == 0) {
        int v = warp_tot[lane];
#pragma unroll
        for (int off = 1; off < 32; off <<= 1) {
            int u = __shfl_up_sync(FULL, v, off);
            if (lane >= off) v += u;
        }
        warp_tot[lane] = v;
    }
    __syncthreads();
    int base = inc - sum + ((w > 0) ? warp_tot[w - 1] : 0);
    int run = base;
    for (int i = 0; i < PER; i++) {
        int n = start + i;
        if (n < NN) { g_offs[n] = run; run += g_deg_in[n]; }
    }
    if (tid == 1023) g_offs[NN] = base;
}

__global__ void k_scatter(const int* __restrict__ esrc, const int* __restrict__ edst) {
    int e = blockIdx.x * blockDim.x + threadIdx.x;
    if (e < NE) {
        int d = edst[e];
        int pos = g_offs[d] + atomicAdd(&g_cursor[d], 1);
        g_csr[pos] = esrc[e];
    }
}

// ---------------- phase 2: warp handles 4 nodes (as 2 pairs); fused gconv ----------------
// R11 structure, gather pinned at 4-wide (8-wide measured neutral/negative).
template<int MODE>
__global__ __launch_bounds__(256) void k_gconv(
    const float* __restrict__ W,
    const float* __restrict__ b,
    const float* __restrict__ Wg2)
{
    __shared__ float Wsm[HH * HH];
    __shared__ float bsm[HH];
    __shared__ float w2sm[HH];
    __shared__ __align__(16) float aggsm[8][2][HH];

    int tid = threadIdx.x;
    int wp  = tid >> 5;
    int lane = tid & 31;
    int t = blockIdx.y;

    for (int i = tid; i < HH * HH; i += 256) Wsm[i] = W[i];
    if (tid < HH) {
        bsm[tid] = b[tid];
        if (MODE == 1) w2sm[tid] = Wg2[tid];
    }
    __syncthreads();

    const __half2* __restrict__ Xt =
        ((MODE == 0) ? g_Hh : g_Zh) + (size_t)t * NN * 32;

    for (int p = 0; p < 2; p++) {
        int nodeA = blockIdx.x * 32 + wp * 4 + 2 * p;
        int nodeB = nodeA + 1;

#pragma unroll
        for (int s = 0; s < 2; s++) {
            int node = nodeA + s;
            if (node < NN) {
                int rs = g_offs[node], re = g_offs[node + 1];
                float ax0 = 0.f, ay0 = 0.f, ax1 = 0.f, ay1 = 0.f;
                for (int base = rs; base < re; base += 32) {
                    int nloc = min(32, re - base);
                    int idx = (lane < nloc) ? g_csr[base + lane] : 0;
                    int j = 0;
                    for (; j + 4 <= nloc; j += 4) {
                        int s0 = __shfl_sync(FULL, idx, j + 0);
                        int s1 = __shfl_sync(FULL, idx, j + 1);
                        int s2 = __shfl_sync(FULL, idx, j + 2);
                        int s3 = __shfl_sync(FULL, idx, j + 3);
                        float2 v0 = __half22float2(Xt[(size_t)s0 * 32 + lane]);
                        float2 v1 = __half22float2(Xt[(size_t)s1 * 32 + lane]);
                        float2 v2 = __half22float2(Xt[(size_t)s2 * 32 + lane]);
                        float2 v3 = __half22float2(Xt[(size_t)s3 * 32 + lane]);
                        ax0 += v0.x + v1.x; ay0 += v0.y + v1.y;
                        ax1 += v2.x + v3.x; ay1 += v2.y + v3.y;
                    }
                    for (; j < nloc; j++) {
                        int sx = __shfl_sync(FULL, idx, j);
                        float2 v = __half22float2(Xt[(size_t)sx * 32 + lane]);
                        ax0 += v.x; ay0 += v.y;
                    }
                }
                float nd = g_ndst[node];
                aggsm[wp][s][2 * lane + 0] = (ax0 + ax1) * nd;
                aggsm[wp][s][2 * lane + 1] = (ay0 + ay1) * nd;
            }
        }
        __syncwarp();

        if (nodeA < NN) {
            bool haveB = (nodeB < NN);
            int d0 = 2 * lane;
            float za0 = bsm[d0], za1 = bsm[d0 + 1];
            float zb0 = za0, zb1 = za1;
            const float4* aA = (const float4*)aggsm[wp][0];
            const float4* aB = (const float4*)aggsm[wp][1];
#pragma unroll
            for (int k4 = 0; k4 < 16; k4++) {
                float4 a = aA[k4];
                float4 bb = aB[k4];
                int kb = k4 * 4;
                float2 w0 = ((const float2*)(Wsm + (kb + 0) * HH))[lane];
                float2 w1 = ((const float2*)(Wsm + (kb + 1) * HH))[lane];
                float2 w2 = ((const float2*)(Wsm + (kb + 2) * HH))[lane];
                float2 w3 = ((const float2*)(Wsm + (kb + 3) * HH))[lane];
                za0 = fmaf(a.x, w0.x, za0); za1 = fmaf(a.x, w0.y, za1);
                zb0 = fmaf(bb.x, w0.x, zb0); zb1 = fmaf(bb.x, w0.y, zb1);
                za0 = fmaf(a.y, w1.x, za0); za1 = fmaf(a.y, w1.y, za1);
                zb0 = fmaf(bb.y, w1.x, zb0); zb1 = fmaf(bb.y, w1.y, zb1);
                za0 = fmaf(a.z, w2.x, za0); za1 = fmaf(a.z, w2.y, za1);
                zb0 = fmaf(bb.z, w2.x, zb0); zb1 = fmaf(bb.z, w2.y, zb1);
                za0 = fmaf(a.w, w3.x, za0); za1 = fmaf(a.w, w3.y, za1);
                zb0 = fmaf(bb.w, w3.x, zb0); zb1 = fmaf(bb.w, w3.y, zb1);
            }

            float nsA = g_nsrc[nodeA];
            za0 = fmaxf(za0, 0.0f) * nsA;
            za1 = fmaxf(za1, 0.0f) * nsA;
            float nsB = haveB ? g_nsrc[nodeB] : 0.0f;
            zb0 = fmaxf(zb0, 0.0f) * nsB;
            zb1 = fmaxf(zb1, 0.0f) * nsB;

            if (MODE == 0) {
                g_Zh[((size_t)t * NN + nodeA) * 32 + lane] = __floats2half2_rn(za0, za1);
                if (haveB)
                    g_Zh[((size_t)t * NN + nodeB) * 32 + lane] = __floats2half2_rn(zb0, zb1);
            } else {
                float pa = za0 * w2sm[d0] + za1 * w2sm[d0 + 1];
                float pb = zb0 * w2sm[d0] + zb1 * w2sm[d0 + 1];
#pragma unroll
                for (int off = 16; off >= 1; off >>= 1) {
                    pa += __shfl_xor_sync(FULL, pa, off);
                    pb += __shfl_xor_sync(FULL, pb, off);
                }
                if (lane == 0) {
                    g_P[(size_t)nodeA * TT + t] = pa;
                    if (haveB) g_P[(size_t)nodeB * TT + t] = pb;
                }
            }
        }
        __syncwarp();
    }
}

// ---------------- final: warp-per-node, lane = t ----------------
__global__ __launch_bounds__(256) void k_final(float* __restrict__ out,
                                               const float* __restrict__ bg2) {
    int node = blockIdx.x * 8 + (threadIdx.x >> 5);
    int lane = threadIdx.x & 31;
    if (node >= NN) return;

    int rs = g_offs[node], re = g_offs[node + 1];
    float s0 = 0.f, s1 = 0.f, s2 = 0.f, s3 = 0.f;

    for (int base = rs; base < re; base += 32) {
        int nloc = min(32, re - base);
        int idx = (lane < nloc) ? g_csr[base + lane] : 0;
        int j = 0;
        for (; j + 4 <= nloc; j += 4) {
            int a0 = __shfl_sync(FULL, idx, j + 0);
            int a1 = __shfl_sync(FULL, idx, j + 1);
            int a2 = __shfl_sync(FULL, idx, j + 2);
            int a3 = __shfl_sync(FULL, idx, j + 3);
            s0 += g_P[(size_t)a0 * TT + lane];
            s1 += g_P[(size_t)a1 * TT + lane];
            s2 += g_P[(size_t)a2 * TT + lane];
            s3 += g_P[(size_t)a3 * TT + lane];
        }
        for (; j < nloc; j++) {
            int a = __shfl_sync(FULL, idx, j);
            s0 += g_P[(size_t)a * TT + lane];
        }
    }
    float s = (s0 + s1) + (s2 + s3);
    if (lane < TT)
        out[node * TT + lane] = g_ndst[node] * s + bg2[0];
}

// ---------------- launch ----------------
extern "C" void kernel_launch(void* const* d_in, const int* in_sizes, int n_in,
                              void* d_out, int out_size)
{
    const float* blob = (const float*)d_in[0];
    const float* Wih  = (const float*)d_in[1];
    const float* bih  = (const float*)d_in[2];
    const float* Whh  = (const float*)d_in[3];
    const float* bhh  = (const float*)d_in[4];
    const float* Wg0  = (const float*)d_in[5];
    const float* bg0  = (const float*)d_in[6];
    const float* Wg1  = (const float*)d_in[7];
    const float* bg1  = (const float*)d_in[8];
    const float* Wg2  = (const float*)d_in[9];
    const float* bg2  = (const float*)d_in[10];
    const int*   esrc = (const int*)d_in[11];
    const int*   edst = (const int*)d_in[12];
    float* out = (float*)d_out;

    k_init<<<(NN + 255) / 256, 256>>>();
    k_deg<<<(NE + 255) / 256, 256>>>(esrc, edst);
    k_norm<<<(NN + 255) / 256, 256>>>();

    // LSTM stays in the ncu capture slot
    k_lstm<<<NN, 512>>>(blob, Wih, bih, Whh, bhh);

    k_scan<<<1, 1024>>>();
    k_scatter<<<(NE + 255) / 256, 256>>>(esrc, edst);

    dim3 gg((NN + 31) / 32, TT);
    k_gconv<0><<<gg, 256>>>(Wg0, bg0, nullptr);
    k_gconv<1><<<gg, 256>>>(Wg1, bg1, Wg2);

    k_final<<<(NN + 7) / 8, 256>>>(out, bg2);
}